// round 5
// baseline (speedup 1.0000x reference)
#include <cuda_runtime.h>
#include <cuda_bf16.h>
#include <math.h>

#define BB 16
#define TT 1024
#define VV 4096
#define PP 100
#define LL 128

// scratch (allocation-free rule: __device__ globals)
__device__ float g_scores[BB * PP];
__device__ float g_wers[BB * PP];

// ---------------------------------------------------------------------------
// Kernel 1: path scores (log-softmax normalizer cancels in the per-b softmax,
// so we only need the raw emission gather sum).
// score[b,p] = sum_{t < len[b]} emissions[b, t, paths[b,p,t]]
// ---------------------------------------------------------------------------
__global__ void __launch_bounds__(128) scores_kernel(
    const float* __restrict__ em,
    const int* __restrict__ elen,
    const int* __restrict__ paths)
{
    const int bp = blockIdx.x;          // 0..B*P-1
    const int b  = bp / PP;
    const int len = elen[b];
    const int* pp = paths + (size_t)bp * TT;
    const float* eb = em + (size_t)b * TT * VV;

    float acc = 0.f;
    #pragma unroll 4
    for (int t = threadIdx.x; t < len; t += 128) {
        int tok = pp[t];                              // coalesced
        acc += __ldg(eb + (size_t)t * VV + tok);      // scattered gather
    }
    // block reduce (4 warps)
    #pragma unroll
    for (int o = 16; o; o >>= 1) acc += __shfl_down_sync(0xffffffffu, acc, o);
    __shared__ float ws[4];
    if ((threadIdx.x & 31) == 0) ws[threadIdx.x >> 5] = acc;
    __syncthreads();
    if (threadIdx.x == 0)
        g_scores[bp] = ws[0] + ws[1] + ws[2] + ws[3];
}

// ---------------------------------------------------------------------------
// Kernel 2: CTC-collapse + Levenshtein via Hyyro/Myers bit-parallel DP.
// Pattern = labels[b][0..m), m = labels_length[b] in [64,128] -> 2x u64 words.
// One block per b; shared PEQ table [V][2] u64 = 64KB; one thread per path.
// Valid token (CTC collapse): tok != BLANK(0) && tok != previous raw token,
// restricted to t < emissions_length[b].
// ---------------------------------------------------------------------------
__global__ void __launch_bounds__(128) edit_kernel(
    const int* __restrict__ paths,
    const int* __restrict__ elen,
    const int* __restrict__ labels,
    const int* __restrict__ llen)
{
    extern __shared__ unsigned long long peq[];   // [VV*2]
    const int b = blockIdx.x;
    const int tid = threadIdx.x;

    // zero PEQ
    for (int i = tid; i < VV * 2; i += 128) peq[i] = 0ull;
    __syncthreads();

    const int m = llen[b];                         // 64..128 (uniform per block)
    if (tid < m) {
        int c = labels[b * LL + tid];              // c in [1, V)
        atomicOr(&peq[(size_t)c * 2 + (tid >> 6)], 1ull << (tid & 63));
    }
    __syncthreads();

    if (tid >= PP) return;

    const int len = elen[b];
    const int* pp = paths + ((size_t)(b * PP + tid)) * TT;

    unsigned long long VP0, VP1, VN0 = 0ull, VN1 = 0ull;
    if (m >= 64) {
        VP0 = ~0ull;
        VP1 = (m >= 128) ? ~0ull : ((m > 64) ? ((1ull << (m - 64)) - 1ull) : 0ull);
    } else {
        VP0 = (1ull << m) - 1ull;
        VP1 = 0ull;
    }
    int score = m;
    const bool hiw = (m > 64);          // which word holds bit m-1
    const int mb = (m - 1) & 63;

    int prev = -1;
    // software pipeline: prefetch token + its PEQ entry one step ahead
    int tok = pp[0];
    unsigned long long e0 = peq[(size_t)tok * 2];
    unsigned long long e1 = peq[(size_t)tok * 2 + 1];

    for (int t = 0; t < len; ++t) {
        const int ctok = tok;
        const unsigned long long Eq0 = e0, Eq1 = e1;
        // prefetch next (safe dummy 0 at the end: peq[0] == {0,0})
        const int tn = (t + 1 < len) ? pp[t + 1] : 0;
        tok = tn;
        e0 = peq[(size_t)tn * 2];
        e1 = peq[(size_t)tn * 2 + 1];

        const bool v = (ctok != 0) && (ctok != prev);
        prev = ctok;
        if (v) {
            // 128-bit Hyyro step
            unsigned long long a0 = Eq0 & VP0;
            unsigned long long a1 = Eq1 & VP1;
            unsigned long long s0 = a0 + VP0;
            unsigned long long cr = (s0 < a0) ? 1ull : 0ull;
            unsigned long long s1 = a1 + VP1 + cr;
            unsigned long long D00 = (s0 ^ VP0) | Eq0 | VN0;
            unsigned long long D01 = (s1 ^ VP1) | Eq1 | VN1;
            unsigned long long HP0 = VN0 | ~(D00 | VP0);
            unsigned long long HP1 = VN1 | ~(D01 | VP1);
            unsigned long long HN0 = VP0 & D00;
            unsigned long long HN1 = VP1 & D01;

            unsigned long long HPw = hiw ? HP1 : HP0;
            unsigned long long HNw = hiw ? HN1 : HN0;
            score += (int)((HPw >> mb) & 1ull);
            score -= (int)((HNw >> mb) & 1ull);

            unsigned long long HPs1 = (HP1 << 1) | (HP0 >> 63);
            unsigned long long HPs0 = (HP0 << 1) | 1ull;
            unsigned long long HNs1 = (HN1 << 1) | (HN0 >> 63);
            unsigned long long HNs0 = (HN0 << 1);
            VP0 = HNs0 | ~(D00 | HPs0);
            VP1 = HNs1 | ~(D01 | HPs1);
            VN0 = D00 & HPs0;
            VN1 = D01 & HPs1;
        }
    }
    g_wers[b * PP + tid] = (float)score;
}

// ---------------------------------------------------------------------------
// Kernel 3: per-b softmax over P paths, weighted sum of wers, total sum.
// Single block (trivial: 1600 values).
// ---------------------------------------------------------------------------
__global__ void __launch_bounds__(128) finalize_kernel(float* __restrict__ out)
{
    __shared__ float red[128];
    const int tid = threadIdx.x;
    float total = 0.f;

    for (int b = 0; b < BB; ++b) {
        float s = (tid < PP) ? g_scores[b * PP + tid] : -3.0e38f;
        red[tid] = s; __syncthreads();
        #pragma unroll
        for (int o = 64; o; o >>= 1) {
            if (tid < o) red[tid] = fmaxf(red[tid], red[tid + o]);
            __syncthreads();
        }
        const float mx = red[0];
        __syncthreads();

        const float e  = (tid < PP) ? expf(s - mx) : 0.f;
        const float ew = (tid < PP) ? e * g_wers[b * PP + tid] : 0.f;

        red[tid] = e; __syncthreads();
        #pragma unroll
        for (int o = 64; o; o >>= 1) {
            if (tid < o) red[tid] += red[tid + o];
            __syncthreads();
        }
        const float Z = red[0];
        __syncthreads();

        red[tid] = ew; __syncthreads();
        #pragma unroll
        for (int o = 64; o; o >>= 1) {
            if (tid < o) red[tid] += red[tid + o];
            __syncthreads();
        }
        const float S = red[0];
        __syncthreads();

        total += S / Z;
    }
    if (tid == 0) out[0] = total;
}

// ---------------------------------------------------------------------------
extern "C" void kernel_launch(void* const* d_in, const int* in_sizes, int n_in,
                              void* d_out, int out_size)
{
    const float* em     = (const float*)d_in[0];  // (B,T,V) f32
    const int*   elen   = (const int*)  d_in[1];  // (B,)
    const int*   labels = (const int*)  d_in[2];  // (B,L)
    const int*   llen   = (const int*)  d_in[3];  // (B,)
    const int*   paths  = (const int*)  d_in[4];  // (B,P,T)

    scores_kernel<<<BB * PP, 128>>>(em, elen, paths);

    const int smem = VV * 2 * (int)sizeof(unsigned long long);  // 64 KB
    cudaFuncSetAttribute(edit_kernel,
                         cudaFuncAttributeMaxDynamicSharedMemorySize, smem);
    edit_kernel<<<BB, 128, smem>>>(paths, elen, labels, llen);

    finalize_kernel<<<1, 128>>>((float*)d_out);
}

// round 6
// speedup vs baseline: 1.5919x; 1.5919x over previous
#include <cuda_runtime.h>
#include <cuda_bf16.h>
#include <math.h>

#define BB 16
#define TT 1024
#define VV 4096
#define PP 100
#define LL 128

typedef unsigned long long u64;

// scratch (allocation-free rule: __device__ globals)
__device__ float g_scores[BB * PP];
__device__ float g_wers[BB * PP];

// ---------------------------------------------------------------------------
// Kernel 1: path scores. log-softmax normalizer is p-independent and cancels
// in the per-b softmax over paths, so only the raw emission gather sum matters.
// score[b,p] = sum_{t < len[b]} emissions[b, t, paths[b,p,t]]
// 4 independent accumulators per thread for MLP.
// ---------------------------------------------------------------------------
__global__ void __launch_bounds__(128) scores_kernel(
    const float* __restrict__ em,
    const int* __restrict__ elen,
    const int* __restrict__ paths)
{
    const int bp = blockIdx.x;          // 0..B*P-1
    const int b  = bp / PP;
    const int len = elen[b];
    const int* pp = paths + (size_t)bp * TT;
    const float* eb = em + (size_t)b * TT * VV;

    float a0 = 0.f, a1 = 0.f, a2 = 0.f, a3 = 0.f;
    int t = threadIdx.x;
    for (; t + 384 < len; t += 512) {
        int k0 = pp[t], k1 = pp[t + 128], k2 = pp[t + 256], k3 = pp[t + 384];
        a0 += __ldg(eb + (size_t)(t)       * VV + k0);
        a1 += __ldg(eb + (size_t)(t + 128) * VV + k1);
        a2 += __ldg(eb + (size_t)(t + 256) * VV + k2);
        a3 += __ldg(eb + (size_t)(t + 384) * VV + k3);
    }
    for (; t < len; t += 128)
        a0 += __ldg(eb + (size_t)t * VV + pp[t]);

    float acc = (a0 + a1) + (a2 + a3);
    #pragma unroll
    for (int o = 16; o; o >>= 1) acc += __shfl_down_sync(0xffffffffu, acc, o);
    __shared__ float ws[4];
    if ((threadIdx.x & 31) == 0) ws[threadIdx.x >> 5] = acc;
    __syncthreads();
    if (threadIdx.x == 0)
        g_scores[bp] = ws[0] + ws[1] + ws[2] + ws[3];
}

// ---------------------------------------------------------------------------
// Kernel 2: CTC-collapse + Levenshtein, Hyyro/Myers bit-parallel, 128-bit
// pattern (2x u64 + add.cc carry). One block per b, one thread per path.
// Branchless step (SEL) + deep int4 token prefetch (distance 8 ~ 400cyc)
// + single LDS.128 per PEQ lookup.
// ---------------------------------------------------------------------------
__global__ void __launch_bounds__(128) edit_kernel(
    const int* __restrict__ paths,
    const int* __restrict__ elen,
    const int* __restrict__ labels,
    const int* __restrict__ llen)
{
    extern __shared__ ulonglong2 peq[];   // [VV], 64KB
    const int b = blockIdx.x;
    const int tid = threadIdx.x;

    for (int i = tid; i < VV; i += 128) peq[i] = make_ulonglong2(0ull, 0ull);
    __syncthreads();

    const int m = llen[b];                 // 64..128, uniform per block
    if (tid < m) {
        int c = labels[b * LL + tid];      // c in [1, V)
        u64* w = (u64*)&peq[c];
        atomicOr(&w[tid >> 6], 1ull << (tid & 63));
    }
    __syncthreads();

    const int lane = (tid < PP) ? tid : (PP - 1);     // clamp extras (no store)
    const int len  = elen[b];
    const int lenU = (len + 3) & ~3;
    const int* pp  = paths + (size_t)(b * PP + lane) * TT;

    u64 VP0, VP1, VN0 = 0ull, VN1 = 0ull;
    if (m >= 64) {
        VP0 = ~0ull;
        VP1 = (m >= 128) ? ~0ull : ((m > 64) ? ((1ull << (m - 64)) - 1ull) : 0ull);
    } else {
        VP0 = (1ull << m) - 1ull; VP1 = 0ull;
    }
    int score = m;
    const bool hiw = (m > 64);
    const int  mb  = (m - 1) & 63;

    int prev = -1;
    // token pipeline: cur = tokens[t4..t4+3], nxt = tokens[t4+4..t4+7]
    int4 cur = *(const int4*)(pp);
    int4 nxt = *(const int4*)(pp + 4);
    int tok = cur.x;
    ulonglong2 E = peq[tok];
    u64 e0 = E.x, e1 = E.y;

    for (int t4 = 0; t4 < lenU; t4 += 4) {
        const int4 far = (t4 + 8 < TT) ? *(const int4*)(pp + t4 + 8)
                                       : make_int4(0, 0, 0, 0);
        #pragma unroll
        for (int i = 0; i < 4; ++i) {
            const int ctok = tok;
            const u64 Eq0 = e0, Eq1 = e1;
            // next-token + PEQ prefetch (one token ahead)
            const int tn = (i == 0) ? cur.y : (i == 1) ? cur.z
                         : (i == 2) ? cur.w : nxt.x;
            const ulonglong2 En = peq[tn];
            tok = tn; e0 = En.x; e1 = En.y;

            const bool v = ((t4 + i) < len) & (ctok != 0) & (ctok != prev);
            prev = ctok;

            // 128-bit Hyyro step (unconditional; SEL at the end)
            u64 a0 = Eq0 & VP0, a1 = Eq1 & VP1;
            u64 s0, s1;
            asm("add.cc.u64 %0, %2, %3;\n\t"
                "addc.u64   %1, %4, %5;"
                : "=l"(s0), "=l"(s1)
                : "l"(a0), "l"(VP0), "l"(a1), "l"(VP1));
            const u64 D00 = (s0 ^ VP0) | Eq0 | VN0;
            const u64 D01 = (s1 ^ VP1) | Eq1 | VN1;
            const u64 HP0 = VN0 | ~(D00 | VP0);
            const u64 HP1 = VN1 | ~(D01 | VP1);
            const u64 HN0 = VP0 & D00;
            const u64 HN1 = VP1 & D01;

            const u64 HPw = hiw ? HP1 : HP0;
            const u64 HNw = hiw ? HN1 : HN0;
            const int d = (int)((HPw >> mb) & 1ull) - (int)((HNw >> mb) & 1ull);

            const u64 HPs1 = (HP1 << 1) | (HP0 >> 63);
            const u64 HPs0 = (HP0 << 1) | 1ull;
            const u64 HNs1 = (HN1 << 1) | (HN0 >> 63);
            const u64 HNs0 = (HN0 << 1);
            const u64 nVP0 = HNs0 | ~(D00 | HPs0);
            const u64 nVP1 = HNs1 | ~(D01 | HPs1);
            const u64 nVN0 = D00 & HPs0;
            const u64 nVN1 = D01 & HPs1;

            VP0 = v ? nVP0 : VP0;  VP1 = v ? nVP1 : VP1;
            VN0 = v ? nVN0 : VN0;  VN1 = v ? nVN1 : VN1;
            score += v ? d : 0;
        }
        cur = nxt; nxt = far;
    }
    if (tid < PP) g_wers[b * PP + tid] = (float)score;
}

// ---------------------------------------------------------------------------
// Kernel 3: per-b softmax over P paths, weighted sum of wers, total sum.
// ---------------------------------------------------------------------------
__global__ void __launch_bounds__(128) finalize_kernel(float* __restrict__ out)
{
    __shared__ float red[128];
    const int tid = threadIdx.x;
    float total = 0.f;

    for (int b = 0; b < BB; ++b) {
        float s = (tid < PP) ? g_scores[b * PP + tid] : -3.0e38f;
        red[tid] = s; __syncthreads();
        #pragma unroll
        for (int o = 64; o; o >>= 1) {
            if (tid < o) red[tid] = fmaxf(red[tid], red[tid + o]);
            __syncthreads();
        }
        const float mx = red[0];
        __syncthreads();

        const float e  = (tid < PP) ? expf(s - mx) : 0.f;
        const float ew = (tid < PP) ? e * g_wers[b * PP + tid] : 0.f;

        red[tid] = e; __syncthreads();
        #pragma unroll
        for (int o = 64; o; o >>= 1) {
            if (tid < o) red[tid] += red[tid + o];
            __syncthreads();
        }
        const float Z = red[0];
        __syncthreads();

        red[tid] = ew; __syncthreads();
        #pragma unroll
        for (int o = 64; o; o >>= 1) {
            if (tid < o) red[tid] += red[tid + o];
            __syncthreads();
        }
        const float S = red[0];
        __syncthreads();

        total += S / Z;
    }
    if (tid == 0) out[0] = total;
}

// ---------------------------------------------------------------------------
extern "C" void kernel_launch(void* const* d_in, const int* in_sizes, int n_in,
                              void* d_out, int out_size)
{
    const float* em     = (const float*)d_in[0];  // (B,T,V) f32
    const int*   elen   = (const int*)  d_in[1];  // (B,)
    const int*   labels = (const int*)  d_in[2];  // (B,L)
    const int*   llen   = (const int*)  d_in[3];  // (B,)
    const int*   paths  = (const int*)  d_in[4];  // (B,P,T)

    scores_kernel<<<BB * PP, 128>>>(em, elen, paths);

    const int smem = VV * (int)sizeof(ulonglong2);  // 64 KB
    cudaFuncSetAttribute(edit_kernel,
                         cudaFuncAttributeMaxDynamicSharedMemorySize, smem);
    edit_kernel<<<BB, 128, smem>>>(paths, elen, labels, llen);

    finalize_kernel<<<1, 128>>>((float*)d_out);
}

// round 7
// speedup vs baseline: 2.0000x; 1.2564x over previous
#include <cuda_runtime.h>
#include <cuda_bf16.h>
#include <math.h>

#define BB 16
#define TT 1024
#define VV 4096
#define PP 100
#define LL 128

typedef unsigned long long u64;

// scratch (allocation-free rule: __device__ globals)
__device__ float g_scores[BB * PP];
__device__ float g_wers[BB * PP];
__device__ unsigned short g_ctok[BB * PP * TT + 64];  // compacted tokens (u16)
__device__ int g_clen[BB * PP];

// ---------------------------------------------------------------------------
// Kernel 1: CTC-collapse stream compaction. One block per (b,p).
// valid = tok!=0 && tok!=raw_prev && t<len. Output u16 tokens, contiguous.
// ---------------------------------------------------------------------------
__global__ void __launch_bounds__(128) compact_kernel(
    const int* __restrict__ paths,
    const int* __restrict__ elen)
{
    const int bp = blockIdx.x;
    const int b  = bp / PP;
    const int len = elen[b];
    const int* pp = paths + (size_t)bp * TT;
    const int tid = threadIdx.x;
    const int t0 = tid * 8;

    int4 A = *(const int4*)(pp + t0);
    int4 Bv = *(const int4*)(pp + t0 + 4);
    int tok[8] = {A.x, A.y, A.z, A.w, Bv.x, Bv.y, Bv.z, Bv.w};
    const int prev0 = (t0 == 0) ? -1 : __ldg(pp + t0 - 1);

    unsigned flags = 0;
    int cnt = 0;
    #pragma unroll
    for (int i = 0; i < 8; ++i) {
        int pr = (i == 0) ? prev0 : tok[i - 1];
        int v = ((t0 + i) < len) & (tok[i] != 0) & (tok[i] != pr);
        flags |= (unsigned)v << i;
        cnt += v;
    }

    // exclusive offset: warp shuffle scan + cross-warp totals
    const int lane = tid & 31, w = tid >> 5;
    int inc = cnt;
    #pragma unroll
    for (int o = 1; o < 32; o <<= 1) {
        int n = __shfl_up_sync(0xffffffffu, inc, o);
        if (lane >= o) inc += n;
    }
    __shared__ int wtot[4];
    if (lane == 31) wtot[w] = inc;
    __syncthreads();
    int wbase = 0;
    #pragma unroll
    for (int i = 0; i < 4; ++i) wbase += (i < w) ? wtot[i] : 0;
    int base = wbase + inc - cnt;

    unsigned short* out = g_ctok + (size_t)bp * TT;
    #pragma unroll
    for (int i = 0; i < 8; ++i) {
        if ((flags >> i) & 1u) out[base++] = (unsigned short)tok[i];
    }
    if (tid == 0) { /* total after sync */ }
    __syncthreads();
    if (tid == 0) g_clen[bp] = wtot[0] + wtot[1] + wtot[2] + wtot[3];
}

// ---------------------------------------------------------------------------
// Kernel 2 (fused): blocks 0..15 = edit distance, blocks 16..1615 = scores.
// Independent work overlapped on different SMs in one launch.
// ---------------------------------------------------------------------------
__device__ __forceinline__ void scores_body(
    int bp, const float* __restrict__ em, const int* __restrict__ elen,
    const int* __restrict__ paths, void* smem_raw)
{
    const int b   = bp / PP;
    const int len = elen[b];
    const int* pp = paths + (size_t)bp * TT;
    const float* eb = em + (size_t)b * TT * VV;
    const int tid = threadIdx.x;
    const int t0 = tid * 8;

    int4 A = *(const int4*)(pp + t0);
    int4 Bv = *(const int4*)(pp + t0 + 4);
    int tok[8] = {A.x, A.y, A.z, A.w, Bv.x, Bv.y, Bv.z, Bv.w};

    float a0 = 0.f, a1 = 0.f, a2 = 0.f, a3 = 0.f;
    #pragma unroll
    for (int i = 0; i < 8; i += 4) {
        if (t0 + i + 0 < len) a0 += __ldg(eb + (size_t)(t0 + i + 0) * VV + tok[i + 0]);
        if (t0 + i + 1 < len) a1 += __ldg(eb + (size_t)(t0 + i + 1) * VV + tok[i + 1]);
        if (t0 + i + 2 < len) a2 += __ldg(eb + (size_t)(t0 + i + 2) * VV + tok[i + 2]);
        if (t0 + i + 3 < len) a3 += __ldg(eb + (size_t)(t0 + i + 3) * VV + tok[i + 3]);
    }
    float acc = (a0 + a1) + (a2 + a3);
    #pragma unroll
    for (int o = 16; o; o >>= 1) acc += __shfl_down_sync(0xffffffffu, acc, o);
    float* ws = (float*)smem_raw;
    if ((tid & 31) == 0) ws[tid >> 5] = acc;
    __syncthreads();
    if (tid == 0) g_scores[bp] = ws[0] + ws[1] + ws[2] + ws[3];
}

__device__ __forceinline__ void edit_body(
    int b, const int* __restrict__ labels, const int* __restrict__ llen,
    void* smem_raw)
{
    ulonglong2* peq = (ulonglong2*)smem_raw;   // [VV], 64KB
    const int tid = threadIdx.x;

    for (int i = tid; i < VV; i += 128) peq[i] = make_ulonglong2(0ull, 0ull);
    __syncthreads();

    const int m = llen[b];                 // 64..128, uniform per block
    if (tid < m) {
        int c = labels[b * LL + tid];      // c in [1, V)
        u64* w = (u64*)&peq[c];
        atomicOr(&w[tid >> 6], 1ull << (tid & 63));
    }
    __syncthreads();

    const int lane = (tid < PP) ? tid : (PP - 1);
    const int n = g_clen[b * PP + lane];
    const unsigned short* ct = g_ctok + (size_t)(b * PP + lane) * TT;

    // warp-max trip count (lanes differ by ~0-3)
    int nW = n;
    #pragma unroll
    for (int o = 16; o; o >>= 1) nW = max(nW, __shfl_xor_sync(0xffffffffu, nW, o));
    const int nR = (nW + 7) & ~7;

    u64 VP0, VP1, VN0 = 0ull, VN1 = 0ull;
    if (m >= 64) {
        VP0 = ~0ull;
        VP1 = (m >= 128) ? ~0ull : ((m > 64) ? ((1ull << (m - 64)) - 1ull) : 0ull);
    } else {
        VP0 = (1ull << m) - 1ull; VP1 = 0ull;
    }
    int score = m;
    const bool hiw = (m > 64);
    const int  mb  = (m - 1) & 63;

    // token pipeline: 2 groups (16 tokens) of lead
    uint4 tv = *(const uint4*)(ct);
    uint4 tn = *(const uint4*)(ct + 8);

    for (int j8 = 0; j8 < nR; j8 += 8) {
        const uint4 tf = *(const uint4*)(ct + j8 + 16);   // pad-safe (global +64)
        unsigned tw[4] = {tv.x, tv.y, tv.z, tv.w};
        #pragma unroll
        for (int i = 0; i < 8; ++i) {
            const int tok = (int)((tw[i >> 1] >> ((i & 1) * 16)) & 0xFFFu);
            const ulonglong2 E = peq[tok];
            const u64 Eq0 = E.x, Eq1 = E.y;

            // 128-bit Myers step (validated recurrence)
            u64 a0 = Eq0 & VP0, a1 = Eq1 & VP1;
            u64 s0, s1;
            asm("add.cc.u64 %0, %2, %3;\n\t"
                "addc.u64   %1, %4, %5;"
                : "=l"(s0), "=l"(s1)
                : "l"(a0), "l"(VP0), "l"(a1), "l"(VP1));
            const u64 D00 = (s0 ^ VP0) | Eq0 | VN0;
            const u64 D01 = (s1 ^ VP1) | Eq1 | VN1;
            const u64 HP0 = VN0 | ~(D00 | VP0);
            const u64 HP1 = VN1 | ~(D01 | VP1);
            const u64 HN0 = VP0 & D00;
            const u64 HN1 = VP1 & D01;

            const u64 HPw = hiw ? HP1 : HP0;
            const u64 HNw = hiw ? HN1 : HN0;
            const int d = (int)((HPw >> mb) & 1ull) - (int)((HNw >> mb) & 1ull);
            // freeze score past this lane's own length (state may run garbage)
            score += ((j8 + i) < n) ? d : 0;

            const u64 HPs1 = (HP1 << 1) | (HP0 >> 63);
            const u64 HPs0 = (HP0 << 1) | 1ull;
            const u64 HNs1 = (HN1 << 1) | (HN0 >> 63);
            const u64 HNs0 = (HN0 << 1);
            VP0 = HNs0 | ~(D00 | HPs0);
            VP1 = HNs1 | ~(D01 | HPs1);
            VN0 = D00 & HPs0;
            VN1 = D01 & HPs1;
        }
        tv = tn; tn = tf;
    }
    if (tid < PP) g_wers[b * PP + tid] = (float)score;
}

__global__ void __launch_bounds__(128) fused_kernel(
    const float* __restrict__ em,
    const int* __restrict__ elen,
    const int* __restrict__ paths,
    const int* __restrict__ labels,
    const int* __restrict__ llen)
{
    extern __shared__ char smem_raw[];
    if (blockIdx.x < BB)
        edit_body(blockIdx.x, labels, llen, smem_raw);
    else
        scores_body(blockIdx.x - BB, em, elen, paths, smem_raw);
}

// ---------------------------------------------------------------------------
// Kernel 3: per-b softmax over P paths, weighted sum of wers, total sum.
// ---------------------------------------------------------------------------
__global__ void __launch_bounds__(128) finalize_kernel(float* __restrict__ out)
{
    __shared__ float red[128];
    const int tid = threadIdx.x;
    float total = 0.f;

    for (int b = 0; b < BB; ++b) {
        float s = (tid < PP) ? g_scores[b * PP + tid] : -3.0e38f;
        red[tid] = s; __syncthreads();
        #pragma unroll
        for (int o = 64; o; o >>= 1) {
            if (tid < o) red[tid] = fmaxf(red[tid], red[tid + o]);
            __syncthreads();
        }
        const float mx = red[0];
        __syncthreads();

        const float e  = (tid < PP) ? expf(s - mx) : 0.f;
        const float ew = (tid < PP) ? e * g_wers[b * PP + tid] : 0.f;

        red[tid] = e; __syncthreads();
        #pragma unroll
        for (int o = 64; o; o >>= 1) {
            if (tid < o) red[tid] += red[tid + o];
            __syncthreads();
        }
        const float Z = red[0];
        __syncthreads();

        red[tid] = ew; __syncthreads();
        #pragma unroll
        for (int o = 64; o; o >>= 1) {
            if (tid < o) red[tid] += red[tid + o];
            __syncthreads();
        }
        const float S = red[0];
        __syncthreads();

        total += S / Z;
    }
    if (tid == 0) out[0] = total;
}

// ---------------------------------------------------------------------------
extern "C" void kernel_launch(void* const* d_in, const int* in_sizes, int n_in,
                              void* d_out, int out_size)
{
    const float* em     = (const float*)d_in[0];  // (B,T,V) f32
    const int*   elen   = (const int*)  d_in[1];  // (B,)
    const int*   labels = (const int*)  d_in[2];  // (B,L)
    const int*   llen   = (const int*)  d_in[3];  // (B,)
    const int*   paths  = (const int*)  d_in[4];  // (B,P,T)

    compact_kernel<<<BB * PP, 128>>>(paths, elen);

    const int smem = VV * (int)sizeof(ulonglong2);  // 64 KB
    cudaFuncSetAttribute(fused_kernel,
                         cudaFuncAttributeMaxDynamicSharedMemorySize, smem);
    fused_kernel<<<BB + BB * PP, 128, smem>>>(em, elen, paths, labels, llen);

    finalize_kernel<<<1, 128>>>((float*)d_out);
}

// round 9
// speedup vs baseline: 2.0006x; 1.0003x over previous
#include <cuda_runtime.h>
#include <cuda_bf16.h>
#include <math.h>

#define BB 16
#define TT 1024
#define VV 4096
#define PP 100
#define LL 128

typedef unsigned long long u64;

// scratch (allocation-free rule: __device__ globals)
__device__ unsigned g_map[BB * VV];                       // per-b vocab -> minpos
__device__ unsigned char g_ctok[BB * PP * TT + 64];       // compacted token ids (u8)
__device__ int g_clen[BB * PP];
__device__ float g_scores[BB * PP];
__device__ float g_wers[BB * PP];
__device__ unsigned g_done;

// ---------------------------------------------------------------------------
// Kernel A: per-b token map. map[b][c] = min label position of char c (else ~0).
// id(c) = map[c]+1 (wraps to 0 for chars not in the label).
// ---------------------------------------------------------------------------
__global__ void __launch_bounds__(128) mapbuild_kernel(
    const int* __restrict__ labels,
    const int* __restrict__ llen)
{
    const int b = blockIdx.x, tid = threadIdx.x;
    uint4* mp = (uint4*)(g_map + (size_t)b * VV);
    const uint4 f = make_uint4(~0u, ~0u, ~0u, ~0u);
    for (int i = tid; i < VV / 4; i += 128) mp[i] = f;
    if (b == 0 && tid == 0) g_done = 0;
    __syncthreads();
    const int m = llen[b];
    if (tid < m)
        atomicMin(&g_map[(size_t)b * VV + labels[b * LL + tid]], (unsigned)tid);
}

// ---------------------------------------------------------------------------
// Kernel B: CTC-collapse + remap to u8 ids. One block per (b,p).
// valid = tok!=0 && tok!=raw_prev && t<len.
// ---------------------------------------------------------------------------
__global__ void __launch_bounds__(128) compact_kernel(
    const int* __restrict__ paths,
    const int* __restrict__ elen)
{
    const int bp = blockIdx.x;
    const int b  = bp / PP;
    const int len = elen[b];
    const int* pp = paths + (size_t)bp * TT;
    const unsigned* map = g_map + (size_t)b * VV;
    const int tid = threadIdx.x;
    const int t0 = tid * 8;

    int4 A = *(const int4*)(pp + t0);
    int4 Bv = *(const int4*)(pp + t0 + 4);
    int tok[8] = {A.x, A.y, A.z, A.w, Bv.x, Bv.y, Bv.z, Bv.w};
    const int prev0 = (t0 == 0) ? -1 : __ldg(pp + t0 - 1);

    unsigned char id[8];
    #pragma unroll
    for (int i = 0; i < 8; ++i)
        id[i] = (unsigned char)(__ldg(map + tok[i]) + 1u);   // 0 if not in label

    unsigned flags = 0;
    int cnt = 0;
    #pragma unroll
    for (int i = 0; i < 8; ++i) {
        int pr = (i == 0) ? prev0 : tok[i - 1];
        int v = ((t0 + i) < len) & (tok[i] != 0) & (tok[i] != pr);
        flags |= (unsigned)v << i;
        cnt += v;
    }

    const int lane = tid & 31, w = tid >> 5;
    int inc = cnt;
    #pragma unroll
    for (int o = 1; o < 32; o <<= 1) {
        int n = __shfl_up_sync(0xffffffffu, inc, o);
        if (lane >= o) inc += n;
    }
    __shared__ int wtot[4];
    if (lane == 31) wtot[w] = inc;
    __syncthreads();
    int wbase = 0;
    #pragma unroll
    for (int i = 0; i < 4; ++i) wbase += (i < w) ? wtot[i] : 0;
    int base = wbase + inc - cnt;

    unsigned char* out = g_ctok + (size_t)bp * TT;
    #pragma unroll
    for (int i = 0; i < 8; ++i)
        if ((flags >> i) & 1u) out[base++] = id[i];
    __syncthreads();
    if (tid == 0) g_clen[bp] = wtot[0] + wtot[1] + wtot[2] + wtot[3];
}

// ---------------------------------------------------------------------------
// Fused kernel: blocks 0..15 = edit distance, rest = scores; last finishing
// block runs the finalize reduction.
// ---------------------------------------------------------------------------
__device__ __forceinline__ void scores_body(
    int bp, const float* __restrict__ em, const int* __restrict__ elen,
    const int* __restrict__ paths, char* smem_raw)
{
    const int b   = bp / PP;
    const int len = elen[b];
    const int* pp = paths + (size_t)bp * TT;
    const float* eb = em + (size_t)b * TT * VV;
    const int tid = threadIdx.x;
    const int t0 = tid * 8;

    int4 A = *(const int4*)(pp + t0);
    int4 Bv = *(const int4*)(pp + t0 + 4);
    int tok[8] = {A.x, A.y, A.z, A.w, Bv.x, Bv.y, Bv.z, Bv.w};

    float a0 = 0.f, a1 = 0.f, a2 = 0.f, a3 = 0.f;
    #pragma unroll
    for (int i = 0; i < 8; i += 4) {
        if (t0 + i + 0 < len) a0 += __ldg(eb + (size_t)(t0 + i + 0) * VV + tok[i + 0]);
        if (t0 + i + 1 < len) a1 += __ldg(eb + (size_t)(t0 + i + 1) * VV + tok[i + 1]);
        if (t0 + i + 2 < len) a2 += __ldg(eb + (size_t)(t0 + i + 2) * VV + tok[i + 2]);
        if (t0 + i + 3 < len) a3 += __ldg(eb + (size_t)(t0 + i + 3) * VV + tok[i + 3]);
    }
    float acc = (a0 + a1) + (a2 + a3);
    #pragma unroll
    for (int o = 16; o; o >>= 1) acc += __shfl_down_sync(0xffffffffu, acc, o);
    float* ws = (float*)smem_raw;
    if ((tid & 31) == 0) ws[tid >> 5] = acc;
    __syncthreads();
    if (tid == 0) g_scores[bp] = ws[0] + ws[1] + ws[2] + ws[3];
    __syncthreads();
}

__device__ __forceinline__ void edit_body(
    int b, const int* __restrict__ labels, const int* __restrict__ llen,
    char* smem_raw)
{
    ulonglong2* peq = (ulonglong2*)smem_raw;   // 256 entries = 4KB
    const int tid = threadIdx.x;

    for (int i = tid; i < 256; i += 128) peq[i] = make_ulonglong2(0ull, 0ull);
    __syncthreads();

    const int m = llen[b];                 // 64..128, uniform per block
    if (tid < m) {
        int c = labels[b * LL + tid];
        unsigned mp = __ldg(&g_map[(size_t)b * VV + c]);     // <= tid
        u64* w = (u64*)&peq[mp + 1];
        atomicOr(&w[tid >> 6], 1ull << (tid & 63));
    }
    __syncthreads();

    const int lane = (tid < PP) ? tid : (PP - 1);
    const int n = g_clen[b * PP + lane];
    const unsigned char* ct = g_ctok + (size_t)(b * PP + lane) * TT;

    int nW = n;
    #pragma unroll
    for (int o = 16; o; o >>= 1) nW = max(nW, __shfl_xor_sync(0xffffffffu, nW, o));
    const int nR = (nW + 15) & ~15;

    u64 VP0, VP1, VN0 = 0ull, VN1 = 0ull;
    VP0 = ~0ull;
    VP1 = (m >= 128) ? ~0ull : ((m > 64) ? ((1ull << (m - 64)) - 1ull) : 0ull);
    int score = m;
    const bool hiw = (m > 64);
    const int  mb  = (m - 1) & 63;

    uint4 tv = *(const uint4*)(ct);
    uint4 tn = *(const uint4*)(ct + 16);

    for (int j = 0; j < nR; j += 16) {
        const uint4 tf = *(const uint4*)(ct + j + 32);   // pad-safe (+64 global pad)
        unsigned tw[4] = {tv.x, tv.y, tv.z, tv.w};
        #pragma unroll
        for (int i = 0; i < 16; ++i) {
            const int id = __byte_perm(tw[i >> 2], 0, 0x4440 | (i & 3));
            const ulonglong2 E = peq[id];                // mostly id==0 -> broadcast
            const u64 Eq0 = E.x, Eq1 = E.y;

            u64 a0 = Eq0 & VP0, a1 = Eq1 & VP1;
            u64 s0, s1;
            asm("add.cc.u64 %0, %2, %3;\n\t"
                "addc.u64   %1, %4, %5;"
                : "=l"(s0), "=l"(s1)
                : "l"(a0), "l"(VP0), "l"(a1), "l"(VP1));
            const u64 D00 = (s0 ^ VP0) | Eq0 | VN0;
            const u64 D01 = (s1 ^ VP1) | Eq1 | VN1;
            const u64 HP0 = VN0 | ~(D00 | VP0);
            const u64 HP1 = VN1 | ~(D01 | VP1);
            const u64 HN0 = VP0 & D00;
            const u64 HN1 = VP1 & D01;

            const u64 HPw = hiw ? HP1 : HP0;
            const u64 HNw = hiw ? HN1 : HN0;
            const int d = (int)((HPw >> mb) & 1ull) - (int)((HNw >> mb) & 1ull);
            score += ((j + i) < n) ? d : 0;

            // 128-bit shift-left-1 via self-add (lets ptxas use add pipes)
            u64 HPs0, HPs1, HNs0, HNs1;
            asm("add.cc.u64 %0, %2, %2;\n\t"
                "addc.u64   %1, %3, %3;"
                : "=l"(HPs0), "=l"(HPs1) : "l"(HP0), "l"(HP1));
            HPs0 |= 1ull;
            asm("add.cc.u64 %0, %2, %2;\n\t"
                "addc.u64   %1, %3, %3;"
                : "=l"(HNs0), "=l"(HNs1) : "l"(HN0), "l"(HN1));

            VP0 = HNs0 | ~(D00 | HPs0);
            VP1 = HNs1 | ~(D01 | HPs1);
            VN0 = D00 & HPs0;
            VN1 = D01 & HPs1;
        }
        tv = tn; tn = tf;
    }
    if (tid < PP) g_wers[b * PP + tid] = (float)score;
    __syncthreads();
}

__device__ __forceinline__ void finalize_body(float* out, char* smem_raw)
{
    float* red = (float*)smem_raw;
    const int tid = threadIdx.x;
    float total = 0.f;
    __threadfence();

    for (int b = 0; b < BB; ++b) {
        float s = (tid < PP) ? g_scores[b * PP + tid] : -3.0e38f;
        red[tid] = s; __syncthreads();
        #pragma unroll
        for (int o = 64; o; o >>= 1) {
            if (tid < o) red[tid] = fmaxf(red[tid], red[tid + o]);
            __syncthreads();
        }
        const float mx = red[0];
        __syncthreads();

        const float e  = (tid < PP) ? expf(s - mx) : 0.f;
        const float ew = (tid < PP) ? e * g_wers[b * PP + tid] : 0.f;

        red[tid] = e; __syncthreads();
        #pragma unroll
        for (int o = 64; o; o >>= 1) {
            if (tid < o) red[tid] += red[tid + o];
            __syncthreads();
        }
        const float Z = red[0];
        __syncthreads();

        red[tid] = ew; __syncthreads();
        #pragma unroll
        for (int o = 64; o; o >>= 1) {
            if (tid < o) red[tid] += red[tid + o];
            __syncthreads();
        }
        const float S = red[0];
        __syncthreads();

        total += S / Z;
    }
    if (tid == 0) out[0] = total;
}

__global__ void __launch_bounds__(128) fused_kernel(
    const float* __restrict__ em,
    const int* __restrict__ elen,
    const int* __restrict__ paths,
    const int* __restrict__ labels,
    const int* __restrict__ llen,
    float* __restrict__ out)
{
    extern __shared__ char smem_raw[];
    __shared__ unsigned s_rank;

    if (blockIdx.x < BB)
        edit_body(blockIdx.x, labels, llen, smem_raw);
    else
        scores_body(blockIdx.x - BB, em, elen, paths, smem_raw);

    if (threadIdx.x == 0) {
        __threadfence();
        s_rank = atomicAdd(&g_done, 1u);
    }
    __syncthreads();
    if (s_rank == (unsigned)(BB + BB * PP - 1))
        finalize_body(out, smem_raw);
}

// ---------------------------------------------------------------------------
extern "C" void kernel_launch(void* const* d_in, const int* in_sizes, int n_in,
                              void* d_out, int out_size)
{
    const float* em     = (const float*)d_in[0];  // (B,T,V) f32
    const int*   elen   = (const int*)  d_in[1];  // (B,)
    const int*   labels = (const int*)  d_in[2];  // (B,L)
    const int*   llen   = (const int*)  d_in[3];  // (B,)
    const int*   paths  = (const int*)  d_in[4];  // (B,P,T)

    mapbuild_kernel<<<BB, 128>>>(labels, llen);
    compact_kernel<<<BB * PP, 128>>>(paths, elen);

    const int smem = 4096 + 512;   // peq (4KB) / reductions
    fused_kernel<<<BB + BB * PP, 128, smem>>>(em, elen, paths, labels, llen,
                                              (float*)d_out);
}